// round 5
// baseline (speedup 1.0000x reference)
#include <cuda_runtime.h>
#include <math.h>
#include <stdint.h>

// ---------------------------------------------------------------------------
// Performer FAVOR+ cross-attention forward.
// B=8, Nq=1024, Nk=4096, D=512, H=8, DH=64, M=256
// Round 4: cp.async 3-stage tf32 MMA GEMM; all GEMM inputs pre-rounded to
// tf32 so the mainloop has zero cvt and zero register staging.
// ---------------------------------------------------------------------------

#define BATCH 8
#define NQ 1024
#define NK 4096
#define DMODEL 512
#define NH 8
#define DHD 64
#define MF 256
#define BHN 64          // BATCH * NH

#define DN_SCALE 0.35355339059327379f  // 64^-0.25
#define RATIO 0.0625f                  // 256^-0.5
#define EPSF 1e-4f

// -------------------- scratch (static device allocations) ------------------
__device__ float g_xr[BATCH * NQ * DMODEL];         // rounded x, 16 MB
__device__ float g_cr[BATCH * NK * DMODEL];         // rounded context, 64 MB
__device__ float g_WqT[DMODEL * DMODEL];
__device__ float g_WkT[DMODEL * DMODEL];
__device__ float g_WvT[DMODEL * DMODEL];
__device__ float g_WoT[DMODEL * DMODEL];
__device__ float g_projR[MF * DHD];                 // rounded proj [N=256][K=64]
__device__ float g_Q[BATCH * NQ * DMODEL];          // 16 MB (tf32-rounded)
__device__ float g_K[BATCH * NK * DMODEL];          // 64 MB (tf32-rounded)
__device__ float g_V[BATCH * NK * DMODEL];          // 64 MB (tf32-rounded)
__device__ float g_qp[BHN * NQ * MF];               // dashQ -> qp, 64 MB
__device__ float g_kp[(size_t)BHN * NK * MF];       // dashK -> kp, 256 MB
__device__ unsigned g_stabEnc[BHN];
__device__ float g_kcPart[64 * BHN * MF];           // 4 MB
__device__ float g_kc[BHN * MF];
__device__ float g_denom[BHN * NQ];
__device__ float g_ctxPart[4 * BHN * MF * DHD];     // 16 MB
__device__ float g_ctx[BHN * MF * DHD];             // 4 MB (tf32-rounded)
__device__ float g_attn[BATCH * NQ * DMODEL];       // 16 MB (tf32-rounded)

// -------------------- helpers ----------------------------------------------
__device__ __forceinline__ float f2tf32f(float f) {
    uint32_t u;
    asm("cvt.rna.tf32.f32 %0, %1;" : "=r"(u) : "f"(f));
    return __uint_as_float(u);
}

__device__ __forceinline__ unsigned encodeF(float f) {
    unsigned u = __float_as_uint(f);
    return (u & 0x80000000u) ? ~u : (u | 0x80000000u);
}
__device__ __forceinline__ float decodeF(unsigned e) {
    unsigned u = (e & 0x80000000u) ? (e ^ 0x80000000u) : ~e;
    return __uint_as_float(u);
}

#define MMA_TF32(d, a, b)                                               \
    asm volatile(                                                       \
        "mma.sync.aligned.m16n8k8.row.col.f32.tf32.tf32.f32 "           \
        "{%0,%1,%2,%3}, {%4,%5,%6,%7}, {%8,%9}, {%0,%1,%2,%3};\n"       \
        : "+f"(d[0]), "+f"(d[1]), "+f"(d[2]), "+f"(d[3])                \
        : "r"(a[0]), "r"(a[1]), "r"(a[2]), "r"(a[3]),                   \
          "r"(b[0]), "r"(b[1]))

#define LDSM4(r0, r1, r2, r3, addr)                                     \
    asm volatile(                                                       \
        "ldmatrix.sync.aligned.m8n8.x4.shared.b16 {%0,%1,%2,%3}, [%4];" \
        : "=r"(r0), "=r"(r1), "=r"(r2), "=r"(r3) : "r"(addr))

__device__ __forceinline__ void cpAsync16(uint32_t dst, const float* src) {
    asm volatile("cp.async.cg.shared.global [%0], [%1], 16;\n"
                 :: "r"(dst), "l"(src));
}
#define CP_COMMIT() asm volatile("cp.async.commit_group;\n")
#define CP_WAIT1()  asm volatile("cp.async.wait_group 1;\n")

__device__ __forceinline__ float warpRedSum(float v) {
#pragma unroll
    for (int o = 16; o > 0; o >>= 1) v += __shfl_xor_sync(0xffffffffu, v, o);
    return v;
}
__device__ __forceinline__ float warpRedMax(float v) {
#pragma unroll
    for (int o = 16; o > 0; o >>= 1) v = fmaxf(v, __shfl_xor_sync(0xffffffffu, v, o));
    return v;
}
__device__ __forceinline__ float blockSum256(float v) {
    __shared__ float sh[8];
    v = warpRedSum(v);
    int lane = threadIdx.x & 31, w = threadIdx.x >> 5;
    __syncthreads();
    if (lane == 0) sh[w] = v;
    __syncthreads();
    float s = sh[0];
#pragma unroll
    for (int i = 1; i < 8; i++) s += sh[i];
    return s;
}
__device__ __forceinline__ float blockMax256(float v) {
    __shared__ float sh[8];
    v = warpRedMax(v);
    int lane = threadIdx.x & 31, w = threadIdx.x >> 5;
    __syncthreads();
    if (lane == 0) sh[w] = v;
    __syncthreads();
    float m = sh[0];
#pragma unroll
    for (int i = 1; i < 8; i++) m = fmaxf(m, sh[i]);
    return m;
}

// ---------------------------------------------------------------------------
// TF32 tensor-core GEMM with cp.async 3-stage pipeline.
// C = alpha * op(A) @ op(B) (+ bias) (/ rowdiv), row-major C [.. x BN tiles].
// AMODE 0: A is [M,K] row-major (k-contiguous); fragments via ldmatrix.
// AMODE 1: A is [K,M] row-major (m-contiguous); computes A^T@B; scalar frags.
// BMODE 0: B given N-MAJOR as Bn[N][K] (k-contiguous rows, e.g. W^T);
//          fragments via ldmatrix.  (only for BN=128)
// BMODE 1: B is [K,N] row-major (n-contiguous); scalar frags. (only BN=64)
// All inputs must already be tf32-rounded. M%128==0, N==BN*gridx, K%16==0.
// Batched over grid.z: z = (z1*d2 + z2)*d3 + z3.
// roundOut: round outputs to tf32 at store.
// ---------------------------------------------------------------------------
template <int BN, int AMODE, int BMODE>
__global__ __launch_bounds__(128) void tmma3(
    const float* __restrict__ A, const float* __restrict__ B,
    float* __restrict__ C, const float* __restrict__ bias,
    const float* __restrict__ rowdiv, unsigned* __restrict__ maxOut,
    int K, int lda, int ldb, int ldc,
    int d2, int d3,
    long oA1, long oA2, long oA3,
    long oB1, long oB2, long oB3,
    long oC1, long oC2, long oC3,
    long oD2, long oD3,
    float alpha, int roundOut)
{
    constexpr int NSTAGE = 3;
    constexpr int WARPS_N = (BN == 128) ? 2 : 1;
    constexpr int WARPS_M = 4 / WARPS_N;
    constexpr int WM = 128 / (WARPS_M * 16);   // m16 tiles per warp (4 or 2)
    constexpr int WN = BN / WARPS_N;           // 64
    constexpr int NJ = WN / 8;                 // 8
    constexpr int APITCH = AMODE ? 136 : 20;
    constexpr int AWORDS = AMODE ? 16 * 136 : 128 * 20;
    constexpr int BPITCH = BMODE ? (BN + 8) : 20;
    constexpr int BWORDS = BMODE ? 16 * (BN + 8) : BN * 20;

    {
        int z = blockIdx.z;
        int z3 = z % d3;
        int zq = z / d3;
        int z2 = zq % d2;
        int z1 = zq / d2;
        A += z1 * oA1 + z2 * oA2 + z3 * oA3;
        B += z1 * oB1 + z2 * oB2 + z3 * oB3;
        C += z1 * oC1 + z2 * oC2 + z3 * oC3;
        if (rowdiv) rowdiv += z2 * oD2 + z3 * oD3;
    }

    extern __shared__ uint32_t smemRaw[];
    uint32_t* aS = smemRaw;
    uint32_t* bS = smemRaw + NSTAGE * AWORDS;
    const uint32_t aU = (uint32_t)__cvta_generic_to_shared(aS);
    const uint32_t bU = (uint32_t)__cvta_generic_to_shared(bS);
    __shared__ float redMax[4];

    const int tid = threadIdx.x;
    const int lane = tid & 31;
    const int warp = tid >> 5;
    const int warpM = warp / WARPS_N;
    const int warpN = warp % WARPS_N;
    const int gid = lane >> 2;
    const int tig = lane & 3;

    const int m0 = blockIdx.y * 128;
    const int n0 = blockIdx.x * BN;

    const int ldsmRow = (lane & 7) + ((lane >> 3) & 1) * 8;
    const int ldsmK   = (lane >> 4) * 4;

    float acc[WM][NJ][4];
#pragma unroll
    for (int i = 0; i < WM; i++)
#pragma unroll
        for (int j = 0; j < NJ; j++)
#pragma unroll
            for (int r = 0; r < 4; r++) acc[i][j][r] = 0.f;

    const int ntiles = K >> 4;

    auto loadStage = [&](int kt, int stage) {
        const int k0 = kt << 4;
        if (AMODE == 0) {
            const float* src = A + (long)(m0 + tid) * lda + k0;
            uint32_t dst = aU + (uint32_t)(stage * AWORDS + tid * 20) * 4u;
#pragma unroll
            for (int g = 0; g < 4; g++) cpAsync16(dst + g * 16, src + g * 4);
        } else {
            const int row = tid >> 3, c0 = (tid & 7) * 4;
            const float* src = A + (long)(k0 + row) * lda + m0 + c0;
            uint32_t dst = aU + (uint32_t)(stage * AWORDS + row * 136 + c0) * 4u;
#pragma unroll
            for (int j = 0; j < 4; j++) cpAsync16(dst + j * 128, src + j * 32);
        }
        if (BMODE == 0) {
            const float* src = B + (long)(n0 + tid) * ldb + k0;
            uint32_t dst = bU + (uint32_t)(stage * BWORDS + tid * 20) * 4u;
#pragma unroll
            for (int g = 0; g < 4; g++) cpAsync16(dst + g * 16, src + g * 4);
        } else {
            const int row = tid >> 3, c0 = (tid & 7) * 4;
            const float* src = B + (long)(k0 + row) * ldb + n0 + c0;
            uint32_t dst = bU + (uint32_t)(stage * BWORDS + row * BPITCH + c0) * 4u;
#pragma unroll
            for (int j = 0; j < 2; j++) cpAsync16(dst + j * 128, src + j * 32);
        }
    };

    auto computeStage = [&](int stage) {
        const uint32_t aStU = aU + (uint32_t)(stage * AWORDS) * 4u;
        const uint32_t* aStP = aS + stage * AWORDS;
        const uint32_t* bStP = bS + stage * BWORDS;
#pragma unroll
        for (int ks = 0; ks < 16; ks += 8) {
            uint32_t af[WM][4];
            uint32_t bf[NJ][2];
            if (AMODE == 0) {
#pragma unroll
                for (int i = 0; i < WM; i++) {
                    uint32_t addr = aStU + (uint32_t)(((warpM * WM + i) * 16 + ldsmRow) * 20
                                                      + ks + ldsmK) * 4u;
                    LDSM4(af[i][0], af[i][1], af[i][2], af[i][3], addr);
                }
            } else {
#pragma unroll
                for (int i = 0; i < WM; i++) {
                    const int mB = (warpM * WM + i) * 16;
                    af[i][0] = aStP[(ks + tig) * 136 + mB + gid];
                    af[i][1] = aStP[(ks + tig) * 136 + mB + gid + 8];
                    af[i][2] = aStP[(ks + tig + 4) * 136 + mB + gid];
                    af[i][3] = aStP[(ks + tig + 4) * 136 + mB + gid + 8];
                }
            }
            if (BMODE == 0) {
#pragma unroll
                for (int jj = 0; jj < NJ / 2; jj++) {
                    uint32_t addr = bU + (uint32_t)((stage * BWORDS) +
                        (warpN * WN + jj * 16 + ldsmRow) * 20 + ks + ldsmK) * 4u;
                    uint32_t r0, r1, r2, r3;
                    LDSM4(r0, r1, r2, r3, addr);
                    bf[jj * 2][0] = r0; bf[jj * 2 + 1][0] = r1;
                    bf[jj * 2][1] = r2; bf[jj * 2 + 1][1] = r3;
                }
            } else {
#pragma unroll
                for (int j = 0; j < NJ; j++) {
                    const int nB = warpN * WN + j * 8;
                    bf[j][0] = bStP[(ks + tig) * BPITCH + nB + gid];
                    bf[j][1] = bStP[(ks + tig + 4) * BPITCH + nB + gid];
                }
            }
#pragma unroll
            for (int i = 0; i < WM; i++)
#pragma unroll
                for (int j = 0; j < NJ; j++)
                    MMA_TF32(acc[i][j], af[i], bf[j]);
        }
    };

    // prologue
#pragma unroll
    for (int s = 0; s < NSTAGE - 1; s++) {
        if (s < ntiles) loadStage(s, s);
        CP_COMMIT();
    }
    // mainloop
    for (int kt = 0; kt < ntiles; kt++) {
        CP_WAIT1();
        __syncthreads();
        const int pf = kt + NSTAGE - 1;
        if (pf < ntiles) loadStage(pf, pf % NSTAGE);
        CP_COMMIT();
        computeStage(kt % NSTAGE);
    }

    // ---- epilogue ----
    float vmax = -1e30f;
#pragma unroll
    for (int i = 0; i < WM; i++) {
        const int rL = m0 + (warpM * WM + i) * 16 + gid;
        float dv0 = 1.f, dv1 = 1.f;
        if (rowdiv) { dv0 = 1.0f / rowdiv[rL]; dv1 = 1.0f / rowdiv[rL + 8]; }
#pragma unroll
        for (int j = 0; j < NJ; j++) {
            const int col = n0 + warpN * WN + (j >> 1) * 16 + (j & 1) * 8 + tig * 2;
            float v0 = alpha * acc[i][j][0], v1 = alpha * acc[i][j][1];
            float v2 = alpha * acc[i][j][2], v3 = alpha * acc[i][j][3];
            if (maxOut)
                vmax = fmaxf(vmax, fmaxf(fmaxf(v0, v1), fmaxf(v2, v3)));
            if (bias) {
                float2 bv = *(const float2*)(bias + col);
                v0 += bv.x; v1 += bv.y; v2 += bv.x; v3 += bv.y;
            }
            v0 *= dv0; v1 *= dv0; v2 *= dv1; v3 *= dv1;
            if (roundOut) {
                v0 = f2tf32f(v0); v1 = f2tf32f(v1);
                v2 = f2tf32f(v2); v3 = f2tf32f(v3);
            }
            *(float2*)(C + (long)rL * ldc + col) = make_float2(v0, v1);
            *(float2*)(C + (long)(rL + 8) * ldc + col) = make_float2(v2, v3);
        }
    }

    if (maxOut) {
        vmax = warpRedMax(vmax);
        if (lane == 0) redMax[warp] = vmax;
        __syncthreads();
        if (tid == 0) {
            float m = fmaxf(fmaxf(redMax[0], redMax[1]), fmaxf(redMax[2], redMax[3]));
            atomicMax(maxOut + blockIdx.z, encodeF(m));
        }
    }
}

// -------------------- pre-rounding / transpose kernels ---------------------
__global__ void round4(const float4* __restrict__ in, float4* __restrict__ out) {
    long i = (long)blockIdx.x * 256 + threadIdx.x;
    float4 v = in[i];
    v.x = f2tf32f(v.x); v.y = f2tf32f(v.y);
    v.z = f2tf32f(v.z); v.w = f2tf32f(v.w);
    out[i] = v;
}

// out[n][k] = round(in[k][n]), 512x512
__global__ void transpose_round(const float* __restrict__ in, float* __restrict__ out) {
    __shared__ float t[32][33];
    int bx = blockIdx.x * 32, by = blockIdx.y * 32;
    int tx = threadIdx.x;
    for (int i = threadIdx.y; i < 32; i += 8)
        t[i][tx] = in[(by + i) * DMODEL + bx + tx];
    __syncthreads();
    for (int i = threadIdx.y; i < 32; i += 8)
        out[(long)(bx + i) * DMODEL + by + tx] = f2tf32f(t[tx][i]);
}

__global__ void init_stab(unsigned* __restrict__ s) {
    s[threadIdx.x] = 0u;
}

// phi_k fused with diag recompute + k_cumsum partials (tf32-rounded writes).
__global__ __launch_bounds__(256) void phi_k_fused(
    const float* __restrict__ Km, float* __restrict__ kp,
    const unsigned* __restrict__ stabEnc, float* __restrict__ kcPart)
{
    __shared__ float diag[64];
    const int chunk = blockIdx.x, bh = blockIdx.y;
    const int b = bh >> 3, h = bh & 7;
    const int t = threadIdx.x;
    const int s0 = chunk * 64;

    {
        const int r = t >> 2, p = t & 3;
        const float* kr = Km + ((long)(b * NK + s0 + r)) * DMODEL + h * DHD + p * 16;
        float ss = 0.f;
#pragma unroll
        for (int i = 0; i < 4; i++) {
            float4 v = *(const float4*)(kr + i * 4);
            ss += v.x * v.x + v.y * v.y + v.z * v.z + v.w * v.w;
        }
        ss += __shfl_xor_sync(0xffffffffu, ss, 1);
        ss += __shfl_xor_sync(0xffffffffu, ss, 2);
        if (p == 0) diag[r] = ss * 0.0625f;
    }
    __syncthreads();

    const float stab = decodeF(stabEnc[bh]);
    float* kb = kp + ((long)bh * NK + s0) * MF;
    float csum = 0.f;
#pragma unroll 4
    for (int r = 0; r < 64; r++) {
        const long idx = (long)r * MF + t;
        float val = f2tf32f(RATIO * (expf(kb[idx] - diag[r] - stab) + EPSF));
        kb[idx] = val;
        csum += val;
    }
    kcPart[((long)chunk * BHN + bh) * MF + t] = csum;
}

__global__ void kc_final(const float* __restrict__ part, float* __restrict__ kc) {
    int bh = blockIdx.x, t = threadIdx.x;
    float s = 0.f;
    for (int c = 0; c < 64; c++) s += part[((long)c * BHN + bh) * MF + t];
    kc[bh * MF + t] = s;
}

// phi_q fused with denominator (qp . kc), tf32-rounded qp writes.
__global__ __launch_bounds__(256) void phi_q_fused(
    const float* __restrict__ Q, float* __restrict__ dq,
    const float* __restrict__ kc, float* __restrict__ denom)
{
    int r = blockIdx.x;
    int t = threadIdx.x;
    int bh = r >> 10, n = r & 1023;
    int b = bh >> 3, h = bh & 7;
    float val = dq[(long)r * MF + t];
    float x = 0.f;
    if (t < DHD) x = Q[((long)(b * NQ + n)) * DMODEL + h * DHD + t];
    float ss = blockSum256(x * x);
    float mx = blockMax256(val);
    float qv = f2tf32f(RATIO * (expf(val - ss * 0.0625f - mx) + EPSF));
    dq[(long)r * MF + t] = qv;
    float d = blockSum256(qv * kc[bh * MF + t]);
    if (t == 0) denom[r] = d;
}

__global__ void reduce_ctx(const float* __restrict__ p, float* __restrict__ c) {
    int i = blockIdx.x * 256 + threadIdx.x;
    c[i] = f2tf32f((p[i] + p[i + 1048576]) + (p[i + 2097152] + p[i + 3145728]));
}

// ---------------------------------------------------------------------------
extern "C" void kernel_launch(void* const* d_in, const int* in_sizes, int n_in,
                              void* d_out, int out_size)
{
    (void)in_sizes; (void)n_in; (void)out_size;
    const float* x       = (const float*)d_in[0];
    const float* context = (const float*)d_in[1];
    const float* Wq      = (const float*)d_in[2];
    const float* Wk      = (const float*)d_in[3];
    const float* Wv      = (const float*)d_in[4];
    const float* Wo      = (const float*)d_in[5];
    const float* bo      = (const float*)d_in[6];
    const float* proj    = (const float*)d_in[7];
    float* out = (float*)d_out;

    float *xr, *cr, *WqT, *WkT, *WvT, *WoT, *projR;
    float *Q, *K, *V, *qp, *kp, *kcPart, *kc, *denom, *ctxPart, *ctx, *attn;
    unsigned* stabEnc;
    cudaGetSymbolAddress((void**)&xr, g_xr);
    cudaGetSymbolAddress((void**)&cr, g_cr);
    cudaGetSymbolAddress((void**)&WqT, g_WqT);
    cudaGetSymbolAddress((void**)&WkT, g_WkT);
    cudaGetSymbolAddress((void**)&WvT, g_WvT);
    cudaGetSymbolAddress((void**)&WoT, g_WoT);
    cudaGetSymbolAddress((void**)&projR, g_projR);
    cudaGetSymbolAddress((void**)&Q, g_Q);
    cudaGetSymbolAddress((void**)&K, g_K);
    cudaGetSymbolAddress((void**)&V, g_V);
    cudaGetSymbolAddress((void**)&qp, g_qp);
    cudaGetSymbolAddress((void**)&kp, g_kp);
    cudaGetSymbolAddress((void**)&stabEnc, g_stabEnc);
    cudaGetSymbolAddress((void**)&kcPart, g_kcPart);
    cudaGetSymbolAddress((void**)&kc, g_kc);
    cudaGetSymbolAddress((void**)&denom, g_denom);
    cudaGetSymbolAddress((void**)&ctxPart, g_ctxPart);
    cudaGetSymbolAddress((void**)&ctx, g_ctx);
    cudaGetSymbolAddress((void**)&attn, g_attn);

    // opt-in to >48KB dynamic smem for the BN=128 instantiation
    const int SM128 = 3 * (128 * 20 + 128 * 20) * 4;   // 61440
    const int SMCTX = 3 * (16 * 136 + 16 * 72) * 4;    // 39936
    const int SMQC  = 3 * (128 * 20 + 16 * 72) * 4;    // 44544
    cudaFuncSetAttribute(tmma3<128, 0, 0>,
                         cudaFuncAttributeMaxDynamicSharedMemorySize, SM128);

    // pre-round inputs to tf32
    round4<<<4096, 256>>>((const float4*)x, (float4*)xr);          // 4M elems
    round4<<<16384, 256>>>((const float4*)context, (float4*)cr);   // 16M elems
    round4<<<16, 256>>>((const float4*)proj, (float4*)projR);      // 16K elems
    transpose_round<<<dim3(16, 16), dim3(32, 8)>>>(Wq, WqT);
    transpose_round<<<dim3(16, 16), dim3(32, 8)>>>(Wk, WkT);
    transpose_round<<<dim3(16, 16), dim3(32, 8)>>>(Wv, WvT);
    transpose_round<<<dim3(16, 16), dim3(32, 8)>>>(Wo, WoT);
    init_stab<<<1, BHN>>>(stabEnc);

    // Q/K/V projections (rounded outputs)
    tmma3<128, 0, 0><<<dim3(4, 64, 1), 128, SM128>>>(xr, WqT, Q, nullptr, nullptr, nullptr,
        DMODEL, DMODEL, DMODEL, DMODEL,
        1, 1, 0, 0, 0, 0, 0, 0, 0, 0, 0, 0, 0, 1.f, 1);
    tmma3<128, 0, 0><<<dim3(4, 256, 1), 128, SM128>>>(cr, WkT, K, nullptr, nullptr, nullptr,
        DMODEL, DMODEL, DMODEL, DMODEL,
        1, 1, 0, 0, 0, 0, 0, 0, 0, 0, 0, 0, 0, 1.f, 1);
    tmma3<128, 0, 0><<<dim3(4, 256, 1), 128, SM128>>>(cr, WvT, V, nullptr, nullptr, nullptr,
        DMODEL, DMODEL, DMODEL, DMODEL,
        1, 1, 0, 0, 0, 0, 0, 0, 0, 0, 0, 0, 0, 1.f, 1);

    // dashQ[b,h,n,m] = dn * (Q_head @ proj^T),  z = b*8 + h; B = projR [256][64]
    tmma3<128, 0, 0><<<dim3(2, 8, BHN), 128, SM128>>>(Q, projR, qp, nullptr, nullptr, nullptr,
        DHD, DMODEL, DHD, MF,
        8, 8,
        0, (long)NQ * DMODEL, DHD,
        0, 0, 0,
        0, (long)NH * NQ * MF, (long)NQ * MF,
        0, 0, DN_SCALE, 0);

    // dashK[b,h,s,m] + fused global-max into stabEnc
    tmma3<128, 0, 0><<<dim3(2, 32, BHN), 128, SM128>>>(K, projR, kp, nullptr, nullptr, stabEnc,
        DHD, DMODEL, DHD, MF,
        8, 8,
        0, (long)NK * DMODEL, DHD,
        0, 0, 0,
        0, (long)NH * NK * MF, (long)NK * MF,
        0, 0, DN_SCALE, 0);

    // kp -> phi(kp) (rounded) + k_cumsum partials
    phi_k_fused<<<dim3(64, 64), 256>>>(K, kp, stabEnc, kcPart);
    kc_final<<<BHN, 256>>>(kcPart, kc);

    // qp -> phi(qp) (rounded) + denominator
    phi_q_fused<<<BHN * NQ, 256>>>(Q, qp, kc, denom);

    // ctx = kp^T @ V, split-K=4:  z = (split*8 + b)*8 + h
    tmma3<64, 1, 1><<<dim3(1, 2, 256), 128, SMCTX>>>(kp, V, ctxPart, nullptr, nullptr, nullptr,
        1024, MF, DMODEL, DHD,
        8, 8,
        (long)1024 * MF, (long)NH * NK * MF, (long)NK * MF,
        (long)1024 * DMODEL, (long)NK * DMODEL, DHD,
        (long)BHN * MF * DHD, (long)NH * MF * DHD, (long)MF * DHD,
        0, 0, 1.f, 0);
    reduce_ctx<<<4096, 256>>>(ctxPart, ctx);

    // attn = (qp @ ctx) / denom, merged-head layout (rounded).  z = b*8 + h
    tmma3<64, 0, 1><<<dim3(1, 8, BHN), 128, SMQC>>>(qp, ctx, attn, nullptr, denom, nullptr,
        MF, MF, DHD, DMODEL,
        8, 8,
        0, (long)NH * NQ * MF, (long)NQ * MF,
        0, (long)NH * MF * DHD, (long)MF * DHD,
        0, (long)NQ * DMODEL, DHD,
        (long)NH * NQ, NQ, 1.f, 0);

    // final projection + bias
    tmma3<128, 0, 0><<<dim3(4, 64, 1), 128, SM128>>>(attn, WoT, out, bo, nullptr, nullptr,
        DMODEL, DMODEL, DMODEL, DMODEL,
        1, 1, 0, 0, 0, 0, 0, 0, 0, 0, 0, 0, 0, 1.f, 0);
}

// round 6
// speedup vs baseline: 1.2668x; 1.2668x over previous
#include <cuda_runtime.h>
#include <math.h>
#include <stdint.h>

// ---------------------------------------------------------------------------
// Performer FAVOR+ cross-attention forward.
// B=8, Nq=1024, Nk=4096, D=512, H=8, DH=64, M=256
// Round 5: revert R4 (cp.async + pre-round regressed). Base = R3 tmma2.
// New: ctx_fused (dash->phi->kc->ctx in one pass over kp) and dashq_phi
// (dashQ GEMM with fused rowmax/phi/denominator epilogue).
// ---------------------------------------------------------------------------

#define BATCH 8
#define NQ 1024
#define NK 4096
#define DMODEL 512
#define NH 8
#define DHD 64
#define MF 256
#define BHN 64          // BATCH * NH

#define DN_SCALE 0.35355339059327379f  // 64^-0.25
#define RATIO 0.0625f                  // 256^-0.5
#define EPSF 1e-4f

// -------------------- scratch (static device allocations) ------------------
__device__ float g_Q[BATCH * NQ * DMODEL];          // 16 MB
__device__ float g_K[BATCH * NK * DMODEL];          // 64 MB
__device__ float g_V[BATCH * NK * DMODEL];          // 64 MB
__device__ float g_projT[DHD * MF];                 // proj transposed [64][256]
__device__ float g_qp[BHN * NQ * MF];               // phi(dashQ), 64 MB
__device__ float g_kp[(size_t)BHN * NK * MF];       // raw dashK, 256 MB
__device__ unsigned g_stabEnc[BHN];
__device__ float g_kcPart[8 * BHN * MF];
__device__ float g_kc[BHN * MF];
__device__ float g_denom[BHN * NQ];
__device__ float g_ctxPart[8 * BHN * MF * DHD];     // 32 MB
__device__ float g_ctx[BHN * MF * DHD];             // 4 MB
__device__ float g_attn[BATCH * NQ * DMODEL];       // 16 MB

// -------------------- helpers ----------------------------------------------
__device__ __forceinline__ uint32_t f2tf32(float f) {
    uint32_t u;
    asm("cvt.rna.tf32.f32 %0, %1;" : "=r"(u) : "f"(f));
    return u;
}
__device__ __forceinline__ float f2tf32f(float f) {
    return __uint_as_float(f2tf32(f));
}

__device__ __forceinline__ unsigned encodeF(float f) {
    unsigned u = __float_as_uint(f);
    return (u & 0x80000000u) ? ~u : (u | 0x80000000u);
}
__device__ __forceinline__ float decodeF(unsigned e) {
    unsigned u = (e & 0x80000000u) ? (e ^ 0x80000000u) : ~e;
    return __uint_as_float(u);
}

#define MMA_TF32(d, a, b)                                               \
    asm volatile(                                                       \
        "mma.sync.aligned.m16n8k8.row.col.f32.tf32.tf32.f32 "           \
        "{%0,%1,%2,%3}, {%4,%5,%6,%7}, {%8,%9}, {%0,%1,%2,%3};\n"       \
        : "+f"(d[0]), "+f"(d[1]), "+f"(d[2]), "+f"(d[3])                \
        : "r"(a[0]), "r"(a[1]), "r"(a[2]), "r"(a[3]),                   \
          "r"(b[0]), "r"(b[1]))

#define LDSM4(r0, r1, r2, r3, addr)                                     \
    asm volatile(                                                       \
        "ldmatrix.sync.aligned.m8n8.x4.shared.b16 {%0,%1,%2,%3}, [%4];" \
        : "=r"(r0), "=r"(r1), "=r"(r2), "=r"(r3) : "r"(addr))

__device__ __forceinline__ float warpRedMax(float v) {
#pragma unroll
    for (int o = 16; o > 0; o >>= 1) v = fmaxf(v, __shfl_xor_sync(0xffffffffu, v, o));
    return v;
}

// ---------------------------------------------------------------------------
// R3 tmma2 (proven): TF32 GEMM, block 128 x BN x 16, 128 threads, 4 warps.
// ---------------------------------------------------------------------------
template <int BN, bool TRANSA>
__global__ __launch_bounds__(128, 2) void tmma2(
    const float* __restrict__ A, const float* __restrict__ B,
    float* __restrict__ C, const float* __restrict__ bias,
    const float* __restrict__ rowdiv, unsigned* __restrict__ maxOut,
    int K, int lda, int ldb, int ldc,
    int d2, int d3,
    long oA1, long oA2, long oA3,
    long oB1, long oB2, long oB3,
    long oC1, long oC2, long oC3,
    long oD2, long oD3,
    float alpha)
{
    constexpr int WN = BN / 2;
    constexpr int NJ = WN / 8;
    constexpr int NJJ = WN / 16;

    {
        int z = blockIdx.z;
        int z3 = z % d3;
        int zq = z / d3;
        int z2 = zq % d2;
        int z1 = zq / d2;
        A += z1 * oA1 + z2 * oA2 + z3 * oA3;
        B += z1 * oB1 + z2 * oB2 + z3 * oB3;
        C += z1 * oC1 + z2 * oC2 + z3 * oC3;
        if (rowdiv) rowdiv += z2 * oD2 + z3 * oD3;
    }

    __shared__ uint32_t As[2][128][20];
    __shared__ uint32_t Bs[2][BN][20];
    __shared__ float redMax[4];

    const int tid = threadIdx.x;
    const int lane = tid & 31;
    const int warp = tid >> 5;
    const int warpM = warp >> 1;
    const int warpN = warp & 1;
    const int gid = lane >> 2;
    const int tig = lane & 3;

    const int m0 = blockIdx.y * 128;
    const int n0 = blockIdx.x * BN;

    const unsigned asU = (unsigned)__cvta_generic_to_shared(&As[0][0][0]);
    const unsigned bsU = (unsigned)__cvta_generic_to_shared(&Bs[0][0][0]);
    const int ldsmRow = (lane & 7) + ((lane >> 3) & 1) * 8;
    const int ldsmK   = (lane >> 4) * 4;

    float acc[4][NJ][4];
#pragma unroll
    for (int i = 0; i < 4; i++)
#pragma unroll
        for (int j = 0; j < NJ; j++)
#pragma unroll
            for (int r = 0; r < 4; r++) acc[i][j][r] = 0.f;

    const int ntiles = K >> 4;
    float pa[16], pb[16];

    auto loadTile = [&](int k0) {
        if (!TRANSA) {
            const float* Ap = A + (long)(m0 + tid) * lda + k0;
            *(float4*)(pa + 0)  = *(const float4*)(Ap + 0);
            *(float4*)(pa + 4)  = *(const float4*)(Ap + 4);
            *(float4*)(pa + 8)  = *(const float4*)(Ap + 8);
            *(float4*)(pa + 12) = *(const float4*)(Ap + 12);
        } else {
            const float* Ap = A + (long)k0 * lda + m0 + tid;
#pragma unroll
            for (int k = 0; k < 16; k++) pa[k] = Ap[(long)k * lda];
        }
        if (BN == 128) {
            const float* Bp = B + (long)k0 * ldb + n0 + tid;
#pragma unroll
            for (int k = 0; k < 16; k++) pb[k] = Bp[(long)k * ldb];
        } else {
            const float* Bp = B + (long)(k0 + (tid >> 6) * 8) * ldb + n0 + (tid & 63);
#pragma unroll
            for (int k = 0; k < 8; k++) pb[k] = Bp[(long)k * ldb];
        }
    };

    auto storeTile = [&](int buf) {
#pragma unroll
        for (int g = 0; g < 4; g++) {
            uint4 u;
            u.x = f2tf32(pa[g * 4 + 0]); u.y = f2tf32(pa[g * 4 + 1]);
            u.z = f2tf32(pa[g * 4 + 2]); u.w = f2tf32(pa[g * 4 + 3]);
            *(uint4*)&As[buf][tid][g * 4] = u;
        }
        if (BN == 128) {
#pragma unroll
            for (int g = 0; g < 4; g++) {
                uint4 u;
                u.x = f2tf32(pb[g * 4 + 0]); u.y = f2tf32(pb[g * 4 + 1]);
                u.z = f2tf32(pb[g * 4 + 2]); u.w = f2tf32(pb[g * 4 + 3]);
                *(uint4*)&Bs[buf][tid][g * 4] = u;
            }
        } else {
            const int n = tid & 63, kg = (tid >> 6) * 8;
#pragma unroll
            for (int g = 0; g < 2; g++) {
                uint4 u;
                u.x = f2tf32(pb[g * 4 + 0]); u.y = f2tf32(pb[g * 4 + 1]);
                u.z = f2tf32(pb[g * 4 + 2]); u.w = f2tf32(pb[g * 4 + 3]);
                *(uint4*)&Bs[buf][n][kg + g * 4] = u;
            }
        }
    };

    auto computeTile = [&](int buf) {
#pragma unroll
        for (int ks = 0; ks < 16; ks += 8) {
            uint32_t af[4][4];
            uint32_t bf[NJ][2];
#pragma unroll
            for (int i = 0; i < 4; i++) {
                unsigned addr = asU + (unsigned)((buf * 128 * 20 +
                    (warpM * 64 + i * 16 + ldsmRow) * 20 + ks + ldsmK) * 4);
                LDSM4(af[i][0], af[i][1], af[i][2], af[i][3], addr);
            }
#pragma unroll
            for (int jj = 0; jj < NJJ; jj++) {
                unsigned addr = bsU + (unsigned)((buf * BN * 20 +
                    (warpN * WN + jj * 16 + ldsmRow) * 20 + ks + ldsmK) * 4);
                uint32_t r0, r1, r2, r3;
                LDSM4(r0, r1, r2, r3, addr);
                bf[jj * 2][0] = r0; bf[jj * 2 + 1][0] = r1;
                bf[jj * 2][1] = r2; bf[jj * 2 + 1][1] = r3;
            }
#pragma unroll
            for (int i = 0; i < 4; i++)
#pragma unroll
                for (int j = 0; j < NJ; j++)
                    MMA_TF32(acc[i][j], af[i], bf[j]);
        }
    };

    loadTile(0);
    storeTile(0);
    __syncthreads();
    for (int kt = 0; kt < ntiles; kt++) {
        const int buf = kt & 1;
        const bool more = (kt + 1) < ntiles;
        if (more) loadTile((kt + 1) << 4);
        computeTile(buf);
        if (more) storeTile(buf ^ 1);
        __syncthreads();
    }

    float vmax = -1e30f;
#pragma unroll
    for (int i = 0; i < 4; i++) {
        const int rL = m0 + warpM * 64 + i * 16 + gid;
        float dv0 = 1.f, dv1 = 1.f;
        if (rowdiv) { dv0 = 1.0f / rowdiv[rL]; dv1 = 1.0f / rowdiv[rL + 8]; }
#pragma unroll
        for (int j = 0; j < NJ; j++) {
            const int col = n0 + warpN * WN + (j >> 1) * 16 + (j & 1) * 8 + tig * 2;
            float v0 = alpha * acc[i][j][0], v1 = alpha * acc[i][j][1];
            float v2 = alpha * acc[i][j][2], v3 = alpha * acc[i][j][3];
            if (maxOut)
                vmax = fmaxf(vmax, fmaxf(fmaxf(v0, v1), fmaxf(v2, v3)));
            if (bias) {
                float2 bv = *(const float2*)(bias + col);
                v0 += bv.x; v1 += bv.y; v2 += bv.x; v3 += bv.y;
            }
            v0 *= dv0; v1 *= dv0; v2 *= dv1; v3 *= dv1;
            *(float2*)(C + (long)rL * ldc + col) = make_float2(v0, v1);
            *(float2*)(C + (long)(rL + 8) * ldc + col) = make_float2(v2, v3);
        }
    }

    if (maxOut) {
        vmax = warpRedMax(vmax);
        if (lane == 0) redMax[warp] = vmax;
        __syncthreads();
        if (tid == 0) {
            float m = fmaxf(fmaxf(redMax[0], redMax[1]), fmaxf(redMax[2], redMax[3]));
            atomicMax(maxOut + blockIdx.z, encodeF(m));
        }
    }
}

// ---------------------------------------------------------------------------
// ctx_fused: per (split, bh), loop 8 chunks of 64 keys:
//   read raw dash from kp -> phi in smem (diag recomputed from K, stab from
//   stabEnc) -> accumulate kc partial -> MMA phi^T @ V into ctx accumulators.
// 256 threads, 8 warps: warpM 0..3 (64 m each), warpN 0..1 (32 d each).
// Dynamic smem: As[64][264] + Bs[64][72] + diag[64].
// ---------------------------------------------------------------------------
#define CF_AP 264
#define CF_BP 72
__global__ __launch_bounds__(256) void ctx_fused(
    const float* __restrict__ kpDash, const float* __restrict__ Km,
    const float* __restrict__ V, const unsigned* __restrict__ stabEnc,
    float* __restrict__ ctxPart, float* __restrict__ kcPart)
{
    extern __shared__ float sm[];
    float* As = sm;                       // 64 * 264
    float* Bs = As + 64 * CF_AP;          // 64 * 72
    float* diag = Bs + 64 * CF_BP;        // 64
    const uint32_t* AsU = (const uint32_t*)As;
    const uint32_t* BsU = (const uint32_t*)Bs;

    const int split = blockIdx.x, bh = blockIdx.y;
    const int b = bh >> 3, h = bh & 7;
    const int t = threadIdx.x;
    const int lane = t & 31, warp = t >> 5;
    const int warpM = warp >> 1;          // 0..3
    const int warpN = warp & 1;           // 0..1
    const int gid = lane >> 2, tig = lane & 3;
    const float stab = decodeF(stabEnc[bh]);
    const int sBase = split * 512;

    float acc[4][4][4];
#pragma unroll
    for (int i = 0; i < 4; i++)
#pragma unroll
        for (int j = 0; j < 4; j++)
#pragma unroll
            for (int r = 0; r < 4; r++) acc[i][j][r] = 0.f;
    float kcLoc = 0.f;

    for (int chunk = 0; chunk < 8; chunk++) {
        const int s0 = sBase + chunk * 64;
        __syncthreads();   // previous MMA done before overwriting As/Bs

        // load dash tile [64 s][256 m]
        const float* dsrc = kpDash + ((long)bh * NK + s0) * MF;
#pragma unroll
        for (int i = 0; i < 16; i++) {
            int linear = i * 256 + t;
            int s = linear >> 6, c4 = linear & 63;
            float4 v = *(const float4*)(dsrc + (long)s * MF + c4 * 4);
            *(float4*)(As + s * CF_AP + c4 * 4) = v;
        }
        // diag for these 64 rows (4 threads per row)
        {
            int r = t >> 2, p = t & 3;
            const float* kr = Km + ((long)(b * NK + s0 + r)) * DMODEL + h * DHD + p * 16;
            float ss = 0.f;
#pragma unroll
            for (int i = 0; i < 4; i++) {
                float4 v = *(const float4*)(kr + i * 4);
                ss += v.x * v.x + v.y * v.y + v.z * v.z + v.w * v.w;
            }
            ss += __shfl_xor_sync(0xffffffffu, ss, 1);
            ss += __shfl_xor_sync(0xffffffffu, ss, 2);
            if (p == 0) diag[r] = ss * 0.0625f;
        }
        // load V tile [64 s][64 d] (tf32-rounded)
        const float* vsrc = V + ((long)(b * NK + s0)) * DMODEL + h * DHD;
#pragma unroll
        for (int i = 0; i < 4; i++) {
            int linear = i * 256 + t;
            int s = linear >> 4, c4 = linear & 15;
            float4 v = *(const float4*)(vsrc + (long)s * DMODEL + c4 * 4);
            v.x = f2tf32f(v.x); v.y = f2tf32f(v.y);
            v.z = f2tf32f(v.z); v.w = f2tf32f(v.w);
            *(float4*)(Bs + s * CF_BP + c4 * 4) = v;
        }
        __syncthreads();

        // phi in place: thread t owns column m = t
        {
            float csum = 0.f;
#pragma unroll 8
            for (int s = 0; s < 64; s++) {
                float val = As[s * CF_AP + t];
                val = RATIO * (__expf(val - diag[s] - stab) + EPSF);
                csum += val;
                As[s * CF_AP + t] = f2tf32f(val);
            }
            kcLoc += csum;
        }
        __syncthreads();

        // MMA: C[m][d] += sum_s phi[s][m] * V[s][d], K=64 (8 k8-steps)
#pragma unroll
        for (int ks = 0; ks < 64; ks += 8) {
            uint32_t af[4][4], bf[4][2];
#pragma unroll
            for (int i = 0; i < 4; i++) {
                const int mB = warpM * 64 + i * 16;
                af[i][0] = AsU[(ks + tig) * CF_AP + mB + gid];
                af[i][1] = AsU[(ks + tig) * CF_AP + mB + gid + 8];
                af[i][2] = AsU[(ks + tig + 4) * CF_AP + mB + gid];
                af[i][3] = AsU[(ks + tig + 4) * CF_AP + mB + gid + 8];
            }
#pragma unroll
            for (int j = 0; j < 4; j++) {
                const int nB = warpN * 32 + j * 8;
                bf[j][0] = BsU[(ks + tig) * CF_BP + nB + gid];
                bf[j][1] = BsU[(ks + tig + 4) * CF_BP + nB + gid];
            }
#pragma unroll
            for (int i = 0; i < 4; i++)
#pragma unroll
                for (int j = 0; j < 4; j++)
                    MMA_TF32(acc[i][j], af[i], bf[j]);
        }
    }

    // epilogue: ctxPart[(split*64+bh)][m][d], kcPart[(split*64+bh)][m]
    float* cp = ctxPart + ((long)(split * BHN + bh)) * MF * DHD;
#pragma unroll
    for (int i = 0; i < 4; i++) {
        const int m = warpM * 64 + i * 16 + gid;
#pragma unroll
        for (int j = 0; j < 4; j++) {
            const int d = warpN * 32 + j * 8 + tig * 2;
            *(float2*)(cp + (long)m * DHD + d) = make_float2(acc[i][j][0], acc[i][j][1]);
            *(float2*)(cp + (long)(m + 8) * DHD + d) = make_float2(acc[i][j][2], acc[i][j][3]);
        }
    }
    kcPart[((long)(split * BHN + bh)) * MF + t] = kcLoc;
}

// ---------------------------------------------------------------------------
// dashq_phi: per (rowtile, bh): dashQ 128x256 GEMM (K=64) with fused epilogue:
//   rowmax over full row, diag recomputed from Q, phi, denominator = phi.kc.
// 256 threads, 8 warps: warpM 0..1 (64 rows), warpN 0..3 (64 cols).
// Dynamic smem: As[128][68] + Bs[256][68] + diag[128] + kcS[256] + red[512]x2.
// ---------------------------------------------------------------------------
#define DQ_P 68
__global__ __launch_bounds__(256) void dashq_phi(
    const float* __restrict__ Q, const float* __restrict__ proj,
    const float* __restrict__ kc, float* __restrict__ qp,
    float* __restrict__ denom)
{
    extern __shared__ float sm[];
    float* As = sm;                        // 128 * 68
    float* Bs = As + 128 * DQ_P;           // 256 * 68
    float* diag = Bs + 256 * DQ_P;         // 128
    float* kcS = diag + 128;               // 256
    float* redA = kcS + 256;               // 128 * 4
    float* redB = redA + 512;              // 128 * 4

    const int rt = blockIdx.x, bh = blockIdx.y;
    const int b = bh >> 3, h = bh & 7;
    const int n0 = rt * 128;
    const int t = threadIdx.x;
    const int lane = t & 31, warp = t >> 5;
    const int warpM = warp >> 2;          // 0..1
    const int warpN = warp & 3;           // 0..3
    const int gid = lane >> 2, tig = lane & 3;
    const unsigned asU = (unsigned)__cvta_generic_to_shared(As);
    const unsigned bsU = (unsigned)__cvta_generic_to_shared(Bs);
    const int ldsmRow = (lane & 7) + ((lane >> 3) & 1) * 8;
    const int ldsmK   = (lane >> 4) * 4;

    // stage A = Q head rows [128 n][64 k] (tf32-rounded)
#pragma unroll
    for (int i = 0; i < 8; i++) {
        int linear = i * 256 + t;
        int n = linear >> 4, c4 = linear & 15;
        float4 v = *(const float4*)(Q + ((long)(b * NQ + n0 + n)) * DMODEL + h * DHD + c4 * 4);
        v.x = f2tf32f(v.x); v.y = f2tf32f(v.y);
        v.z = f2tf32f(v.z); v.w = f2tf32f(v.w);
        *(float4*)(As + n * DQ_P + c4 * 4) = v;
    }
    // stage B = proj [256 m][64 k] n-major (tf32-rounded)
#pragma unroll
    for (int i = 0; i < 16; i++) {
        int linear = i * 256 + t;
        int r = linear >> 4, c4 = linear & 15;
        float4 v = *(const float4*)(proj + (long)r * DHD + c4 * 4);
        v.x = f2tf32f(v.x); v.y = f2tf32f(v.y);
        v.z = f2tf32f(v.z); v.w = f2tf32f(v.w);
        *(float4*)(Bs + r * DQ_P + c4 * 4) = v;
    }
    // diag: 2 threads per row
    {
        int r = t >> 1, half = t & 1;
        const float* qr = Q + ((long)(b * NQ + n0 + r)) * DMODEL + h * DHD + half * 32;
        float ss = 0.f;
#pragma unroll
        for (int i = 0; i < 8; i++) {
            float4 v = *(const float4*)(qr + i * 4);
            ss += v.x * v.x + v.y * v.y + v.z * v.z + v.w * v.w;
        }
        ss += __shfl_xor_sync(0xffffffffu, ss, 1);
        if (half == 0) diag[r] = ss * 0.0625f;
    }
    kcS[t] = kc[bh * MF + t];
    __syncthreads();

    // MMA: dash[n][m] = Q[n][k] * proj[m][k],  M=128, N=256, K=64
    float acc[4][8][4];
#pragma unroll
    for (int i = 0; i < 4; i++)
#pragma unroll
        for (int j = 0; j < 8; j++)
#pragma unroll
            for (int r = 0; r < 4; r++) acc[i][j][r] = 0.f;

#pragma unroll
    for (int ks = 0; ks < 64; ks += 8) {
        uint32_t af[4][4], bf[8][2];
#pragma unroll
        for (int i = 0; i < 4; i++) {
            unsigned addr = asU + (unsigned)(((warpM * 64 + i * 16 + ldsmRow) * DQ_P
                                              + ks + ldsmK) * 4);
            LDSM4(af[i][0], af[i][1], af[i][2], af[i][3], addr);
        }
#pragma unroll
        for (int jj = 0; jj < 4; jj++) {
            unsigned addr = bsU + (unsigned)(((warpN * 64 + jj * 16 + ldsmRow) * DQ_P
                                              + ks + ldsmK) * 4);
            uint32_t r0, r1, r2, r3;
            LDSM4(r0, r1, r2, r3, addr);
            bf[jj * 2][0] = r0; bf[jj * 2 + 1][0] = r1;
            bf[jj * 2][1] = r2; bf[jj * 2 + 1][1] = r3;
        }
#pragma unroll
        for (int i = 0; i < 4; i++)
#pragma unroll
            for (int j = 0; j < 8; j++)
                MMA_TF32(acc[i][j], af[i], bf[j]);
    }

    // scale to dash
#pragma unroll
    for (int i = 0; i < 4; i++)
#pragma unroll
        for (int j = 0; j < 8; j++)
#pragma unroll
            for (int r = 0; r < 4; r++) acc[i][j][r] *= DN_SCALE;

    // rowmax: quad (tig) shuffle + cross-warpN smem
#pragma unroll
    for (int i = 0; i < 4; i++) {
        const int rA = warpM * 64 + i * 16 + gid;
        float mA = -1e30f, mB = -1e30f;
#pragma unroll
        for (int j = 0; j < 8; j++) {
            mA = fmaxf(mA, fmaxf(acc[i][j][0], acc[i][j][1]));
            mB = fmaxf(mB, fmaxf(acc[i][j][2], acc[i][j][3]));
        }
        mA = fmaxf(mA, __shfl_xor_sync(0xffffffffu, mA, 1));
        mA = fmaxf(mA, __shfl_xor_sync(0xffffffffu, mA, 2));
        mB = fmaxf(mB, __shfl_xor_sync(0xffffffffu, mB, 1));
        mB = fmaxf(mB, __shfl_xor_sync(0xffffffffu, mB, 2));
        if (tig == 0) {
            redA[rA * 4 + warpN] = mA;
            redA[(rA + 8) * 4 + warpN] = mB;
        }
    }
    __syncthreads();

    // phi + qp store + denominator partials
#pragma unroll
    for (int i = 0; i < 4; i++) {
        const int rA = warpM * 64 + i * 16 + gid;
        const int rB = rA + 8;
        const float rmA = fmaxf(fmaxf(redA[rA * 4], redA[rA * 4 + 1]),
                                fmaxf(redA[rA * 4 + 2], redA[rA * 4 + 3]));
        const float rmB = fmaxf(fmaxf(redA[rB * 4], redA[rB * 4 + 1]),
                                fmaxf(redA[rB * 4 + 2], redA[rB * 4 + 3]));
        const float shA = diag[rA] + rmA;
        const float shB = diag[rB] + rmB;
        float dA = 0.f, dB = 0.f;
#pragma unroll
        for (int j = 0; j < 8; j++) {
            const int col = warpN * 64 + (j >> 1) * 16 + (j & 1) * 8 + tig * 2;
            float p0 = RATIO * (__expf(acc[i][j][0] - shA) + EPSF);
            float p1 = RATIO * (__expf(acc[i][j][1] - shA) + EPSF);
            float p2 = RATIO * (__expf(acc[i][j][2] - shB) + EPSF);
            float p3 = RATIO * (__expf(acc[i][j][3] - shB) + EPSF);
            float2 kv = *(const float2*)(kcS + col);
            dA += p0 * kv.x + p1 * kv.y;
            dB += p2 * kv.x + p3 * kv.y;
            *(float2*)(qp + ((long)bh * NQ + n0 + rA) * MF + col) = make_float2(p0, p1);
            *(float2*)(qp + ((long)bh * NQ + n0 + rB) * MF + col) = make_float2(p2, p3);
        }
        dA += __shfl_xor_sync(0xffffffffu, dA, 1);
        dA += __shfl_xor_sync(0xffffffffu, dA, 2);
        dB += __shfl_xor_sync(0xffffffffu, dB, 1);
        dB += __shfl_xor_sync(0xffffffffu, dB, 2);
        if (tig == 0) {
            redB[rA * 4 + warpN] = dA;
            redB[rB * 4 + warpN] = dB;
        }
    }
    __syncthreads();
    if (warpN == 0 && tig == 0) {
#pragma unroll
        for (int i = 0; i < 4; i++) {
            const int rA = warpM * 64 + i * 16 + gid;
            const int rB = rA + 8;
            denom[(long)bh * NQ + n0 + rA] =
                (redB[rA * 4] + redB[rA * 4 + 1]) + (redB[rA * 4 + 2] + redB[rA * 4 + 3]);
            denom[(long)bh * NQ + n0 + rB] =
                (redB[rB * 4] + redB[rB * 4 + 1]) + (redB[rB * 4 + 2] + redB[rB * 4 + 3]);
        }
    }
}

// -------------------- small kernels ----------------------------------------
__global__ void transpose_proj(const float* __restrict__ proj, float* __restrict__ projT) {
    int i = blockIdx.x * 256 + threadIdx.x;
    int m = i >> 6, d = i & 63;
    projT[d * MF + m] = proj[i];
}

__global__ void init_stab(unsigned* __restrict__ s) {
    s[threadIdx.x] = 0u;
}

__global__ void kc_final8(const float* __restrict__ part, float* __restrict__ kc) {
    int bh = blockIdx.x, t = threadIdx.x;
    float s = 0.f;
#pragma unroll
    for (int sp = 0; sp < 8; sp++) s += part[((long)(sp * BHN + bh)) * MF + t];
    kc[bh * MF + t] = s;
}

__global__ void reduce_ctx8(const float* __restrict__ p, float* __restrict__ c) {
    int i = blockIdx.x * 256 + threadIdx.x;   // 1048576 total
    float s0 = p[i] + p[i + 1 * 1048576];
    float s1 = p[i + 2 * 1048576] + p[i + 3 * 1048576];
    float s2 = p[i + 4 * 1048576] + p[i + 5 * 1048576];
    float s3 = p[i + 6 * 1048576] + p[i + 7 * 1048576];
    c[i] = (s0 + s1) + (s2 + s3);
}

// ---------------------------------------------------------------------------
extern "C" void kernel_launch(void* const* d_in, const int* in_sizes, int n_in,
                              void* d_out, int out_size)
{
    (void)in_sizes; (void)n_in; (void)out_size;
    const float* x       = (const float*)d_in[0];
    const float* context = (const float*)d_in[1];
    const float* Wq      = (const float*)d_in[2];
    const float* Wk      = (const float*)d_in[3];
    const float* Wv      = (const float*)d_in[4];
    const float* Wo      = (const float*)d_in[5];
    const float* bo      = (const float*)d_in[6];
    const float* proj    = (const float*)d_in[7];
    float* out = (float*)d_out;

    float *Q, *K, *V, *projT, *qp, *kp, *kcPart, *kc, *denom;
    float *ctxPart, *ctx, *attn;
    unsigned* stabEnc;
    cudaGetSymbolAddress((void**)&Q, g_Q);
    cudaGetSymbolAddress((void**)&K, g_K);
    cudaGetSymbolAddress((void**)&V, g_V);
    cudaGetSymbolAddress((void**)&projT, g_projT);
    cudaGetSymbolAddress((void**)&qp, g_qp);
    cudaGetSymbolAddress((void**)&kp, g_kp);
    cudaGetSymbolAddress((void**)&stabEnc, g_stabEnc);
    cudaGetSymbolAddress((void**)&kcPart, g_kcPart);
    cudaGetSymbolAddress((void**)&kc, g_kc);
    cudaGetSymbolAddress((void**)&denom, g_denom);
    cudaGetSymbolAddress((void**)&ctxPart, g_ctxPart);
    cudaGetSymbolAddress((void**)&ctx, g_ctx);
    cudaGetSymbolAddress((void**)&attn, g_attn);

    const int SM_CTX = (64 * CF_AP + 64 * CF_BP + 64) * 4;            // 86272
    const int SM_DQ  = (128 * DQ_P + 256 * DQ_P + 128 + 256 + 1024) * 4;  // 110080
    cudaFuncSetAttribute(ctx_fused, cudaFuncAttributeMaxDynamicSharedMemorySize, SM_CTX);
    cudaFuncSetAttribute(dashq_phi, cudaFuncAttributeMaxDynamicSharedMemorySize, SM_DQ);

    transpose_proj<<<64, 256>>>(proj, projT);
    init_stab<<<1, BHN>>>(stabEnc);

    // Q/K/V projections
    tmma2<128, false><<<dim3(4, 64, 1), 128>>>(x, Wq, Q, nullptr, nullptr, nullptr,
        DMODEL, DMODEL, DMODEL, DMODEL,
        1, 1, 0, 0, 0, 0, 0, 0, 0, 0, 0, 0, 0, 1.f);
    tmma2<128, false><<<dim3(4, 256, 1), 128>>>(context, Wk, K, nullptr, nullptr, nullptr,
        DMODEL, DMODEL, DMODEL, DMODEL,
        1, 1, 0, 0, 0, 0, 0, 0, 0, 0, 0, 0, 0, 1.f);
    tmma2<128, false><<<dim3(4, 256, 1), 128>>>(context, Wv, V, nullptr, nullptr, nullptr,
        DMODEL, DMODEL, DMODEL, DMODEL,
        1, 1, 0, 0, 0, 0, 0, 0, 0, 0, 0, 0, 0, 1.f);

    // dashK raw + fused global max (z = b*8 + h)
    tmma2<128, false><<<dim3(2, 32, BHN), 128>>>(K, projT, kp, nullptr, nullptr, stabEnc,
        DHD, DMODEL, MF, MF,
        8, 8,
        0, (long)NK * DMODEL, DHD,
        0, 0, 0,
        0, (long)NH * NK * MF, (long)NK * MF,
        0, 0, DN_SCALE);

    // fused phi_k + kc partials + ctx accumulation
    ctx_fused<<<dim3(8, 64), 256, SM_CTX>>>(kp, K, V, stabEnc, ctxPart, kcPart);
    reduce_ctx8<<<4096, 256>>>(ctxPart, ctx);
    kc_final8<<<BHN, 256>>>(kcPart, kc);

    // fused dashQ + phi_q + denominator
    dashq_phi<<<dim3(8, 64), 256, SM_DQ>>>(Q, proj, kc, qp, denom);

    // attn = (qp @ ctx) / denom, merged-head layout (z = b*8 + h)
    tmma2<64, false><<<dim3(1, 8, BHN), 128>>>(qp, ctx, attn, nullptr, denom, nullptr,
        MF, MF, DHD, DMODEL,
        8, 8,
        0, (long)NH * NQ * MF, (long)NQ * MF,
        0, (long)NH * MF * DHD, (long)MF * DHD,
        0, (long)NQ * DMODEL, DHD,
        (long)NH * NQ, NQ, 1.f);

    // final projection + bias
    tmma2<128, false><<<dim3(4, 64, 1), 128>>>(attn, Wo, out, bo, nullptr, nullptr,
        DMODEL, DMODEL, DMODEL, DMODEL,
        1, 1, 0, 0, 0, 0, 0, 0, 0, 0, 0, 0, 0, 1.f);
}